// round 1
// baseline (speedup 1.0000x reference)
#include <cuda_runtime.h>
#include <math.h>

#define B_ 4
#define N_ 8192

constexpr int TPB   = 256;              // threads per block
constexpr int PPT   = 4;                // x points per thread (chamfer)
constexpr int XTILES = N_ / (TPB * PPT); // 8
constexpr int NSEG  = 32;               // y segments
constexpr int SEG   = N_ / NSEG;        // 256 y points per segment
constexpr int SL_GRID = 128;            // small-loss blocks

// Scratch (no allocations allowed): min-d2 as int-encoded nonneg floats, partial sums.
__device__ int   g_min[2 * B_ * N_];
__device__ float g_part[3 * SL_GRID];

__global__ void init_min_kernel() {
    int i = blockIdx.x * blockDim.x + threadIdx.x;
    if (i < 2 * B_ * N_) g_min[i] = 0x7F7F7F7F;  // large positive float
}

// vertex MSE + smoothness + symmetry, block partials (deterministic, no atomics)
__global__ void small_losses_kernel(const float* __restrict__ pred,
                                    const float* __restrict__ targ) {
    __shared__ float red[TPB];
    const int tid = threadIdx.x;
    const int gid = blockIdx.x * TPB + tid;
    const int gsz = gridDim.x * TPB;

    // ---- vertex: sum (p - t)^2 over B*N*3 ----
    float s = 0.f;
    for (int i = gid; i < B_ * N_ * 3; i += gsz) {
        float d = pred[i] - targ[i];
        s = fmaf(d, d, s);
    }
    red[tid] = s; __syncthreads();
    for (int o = TPB / 2; o > 0; o >>= 1) {
        if (tid < o) red[tid] += red[tid + o];
        __syncthreads();
    }
    if (tid == 0) g_part[0 * SL_GRID + blockIdx.x] = red[0];
    __syncthreads();

    // ---- smoothness: sum ||p[i+1]-p[i]|| over B*(N-1) ----
    s = 0.f;
    for (int i = gid; i < B_ * (N_ - 1); i += gsz) {
        int b = i / (N_ - 1), k = i % (N_ - 1);
        const float* p = pred + (b * N_ + k) * 3;
        float dx = p[3] - p[0], dy = p[4] - p[1], dz = p[5] - p[2];
        s += sqrtf(fmaf(dx, dx, fmaf(dy, dy, dz * dz)));
    }
    red[tid] = s; __syncthreads();
    for (int o = TPB / 2; o > 0; o >>= 1) {
        if (tid < o) red[tid] += red[tid + o];
        __syncthreads();
    }
    if (tid == 0) g_part[1 * SL_GRID + blockIdx.x] = red[0];
    __syncthreads();

    // ---- symmetry: left[k] vs flipped right, x negated ----
    s = 0.f;
    const int mid = N_ / 2;
    for (int i = gid; i < B_ * mid; i += gsz) {
        int b = i / mid, k = i % mid;
        const float* l = pred + (b * N_ + k) * 3;
        const float* r = pred + (b * N_ + (N_ - 1 - k)) * 3;
        float d0 = l[0] + r[0];     // left.x - (-right.x)
        float d1 = l[1] - r[1];
        float d2 = l[2] - r[2];
        s += fmaf(d0, d0, fmaf(d1, d1, d2 * d2));
    }
    red[tid] = s; __syncthreads();
    for (int o = TPB / 2; o > 0; o >>= 1) {
        if (tid < o) red[tid] += red[tid + o];
        __syncthreads();
    }
    if (tid == 0) g_part[2 * SL_GRID + blockIdx.x] = red[0];
}

// For each x point: min over a y-segment of (||y||^2 - 2 x.y); atomicMin of
// clamped full d2 across segments. Called twice with roles swapped.
__global__ void __launch_bounds__(TPB, 8)
chamfer_kernel(const float* __restrict__ X, const float* __restrict__ Y, int outOff) {
    __shared__ float4 sy[SEG];
    const int b = blockIdx.z;
    const float* Yb = Y + b * N_ * 3;
    const int m0 = blockIdx.y * SEG;

    for (int j = threadIdx.x; j < SEG; j += TPB) {
        const float* y = Yb + (m0 + j) * 3;
        float y0 = y[0], y1 = y[1], y2 = y[2];
        sy[j] = make_float4(y0, y1, y2, fmaf(y0, y0, fmaf(y1, y1, y2 * y2)));
    }
    __syncthreads();

    const float* Xb = X + b * N_ * 3;
    const int n0 = blockIdx.x * (TPB * PPT) + threadIdx.x;

    float x0[PPT], x1[PPT], x2[PPT], xn[PPT], mn[PPT];
#pragma unroll
    for (int p = 0; p < PPT; p++) {
        const float* x = Xb + (n0 + p * TPB) * 3;
        x0[p] = x[0]; x1[p] = x[1]; x2[p] = x[2];
        xn[p] = fmaf(x0[p], x0[p], fmaf(x1[p], x1[p], x2[p] * x2[p]));
        mn[p] = 3.0e38f;
    }

#pragma unroll 4
    for (int j = 0; j < SEG; j++) {
        float4 y = sy[j];
#pragma unroll
        for (int p = 0; p < PPT; p++) {
            float dot = fmaf(x0[p], y.x, fmaf(x1[p], y.y, x2[p] * y.z));
            float s   = fmaf(-2.f, dot, y.w);       // ||y||^2 - 2 x.y
            mn[p] = fminf(mn[p], s);
        }
    }

#pragma unroll
    for (int p = 0; p < PPT; p++) {
        float d2 = fmaxf(xn[p] + mn[p], 0.f);       // nonneg -> int-compare valid
        atomicMin(&g_min[outOff + b * N_ + n0 + p * TPB], __float_as_int(d2));
    }
}

__global__ void finalize_kernel(float* __restrict__ out) {
    __shared__ float red[TPB];
    __shared__ float cham_s;
    const int tid = threadIdx.x;

    // chamfer: sum sqrt(min d2) over both directions (65536 values)
    float s = 0.f;
    for (int i = tid; i < 2 * B_ * N_; i += TPB)
        s += sqrtf(__int_as_float(g_min[i]));
    red[tid] = s; __syncthreads();
    for (int o = TPB / 2; o > 0; o >>= 1) {
        if (tid < o) red[tid] += red[tid + o];
        __syncthreads();
    }
    if (tid == 0) cham_s = red[0];
    __syncthreads();

    // vertex partials
    s = (tid < SL_GRID) ? g_part[0 * SL_GRID + tid] : 0.f;
    red[tid] = s; __syncthreads();
    for (int o = TPB / 2; o > 0; o >>= 1) {
        if (tid < o) red[tid] += red[tid + o];
        __syncthreads();
    }
    float vsum = red[0]; __syncthreads();

    // smoothness partials
    s = (tid < SL_GRID) ? g_part[1 * SL_GRID + tid] : 0.f;
    red[tid] = s; __syncthreads();
    for (int o = TPB / 2; o > 0; o >>= 1) {
        if (tid < o) red[tid] += red[tid + o];
        __syncthreads();
    }
    float smsum = red[0]; __syncthreads();

    // symmetry partials
    s = (tid < SL_GRID) ? g_part[2 * SL_GRID + tid] : 0.f;
    red[tid] = s; __syncthreads();
    for (int o = TPB / 2; o > 0; o >>= 1) {
        if (tid < o) red[tid] += red[tid + o];
        __syncthreads();
    }
    float sysum = red[0];

    if (tid == 0) {
        float vertex_loss   = vsum  / (float)(B_ * N_ * 3);        // 98304
        float smooth_loss   = smsum / (float)(B_ * (N_ - 1));      // 32764
        float sym_loss      = sysum / (float)(B_ * (N_ / 2) * 3);  // 49152
        float chamfer_loss  = cham_s / (float)(B_ * N_);           // meanA + meanB
        out[0] = 1.0f * vertex_loss + 0.1f * smooth_loss
               + 0.05f * sym_loss + 0.1f * chamfer_loss;
    }
}

extern "C" void kernel_launch(void* const* d_in, const int* in_sizes, int n_in,
                              void* d_out, int out_size) {
    const float* pred = (const float*)d_in[0];
    const float* targ = (const float*)d_in[1];
    float* out = (float*)d_out;
    (void)in_sizes; (void)n_in; (void)out_size;

    init_min_kernel<<<(2 * B_ * N_ + 255) / 256, 256>>>();
    small_losses_kernel<<<SL_GRID, TPB>>>(pred, targ);

    dim3 grid(XTILES, NSEG, B_);
    chamfer_kernel<<<grid, TPB>>>(pred, targ, 0);          // min over targets per pred
    chamfer_kernel<<<grid, TPB>>>(targ, pred, B_ * N_);    // min over preds per target

    finalize_kernel<<<1, TPB>>>(out);
}

// round 2
// speedup vs baseline: 1.7396x; 1.7396x over previous
#include <cuda_runtime.h>
#include <math.h>

#define B_ 4
#define N_ 8192

constexpr int TPB    = 256;            // threads per block (chamfer)
constexpr int PPT    = 8;              // x points per thread
constexpr int XPB    = TPB * PPT;      // 2048 x points per block
constexpr int XTILES = N_ / XPB;       // 4
constexpr int NSEG   = 16;             // y segments
constexpr int SEG    = N_ / NSEG;      // 512 y per segment
constexpr int SL_GRID = 128;           // small-loss blocks
constexpr int FTPB   = 1024;           // finalize threads

// Scratch: min-d2 int-encoded (nonneg floats -> int compare valid), partials.
__device__ int   g_min[2 * B_ * N_];
__device__ float g_part[3 * SL_GRID];

union F2 { unsigned long long u; float2 f; };

__device__ __forceinline__ unsigned long long fma2(unsigned long long a,
                                                   unsigned long long b,
                                                   unsigned long long c) {
    unsigned long long d;
    asm("fma.rn.f32x2 %0, %1, %2, %3;" : "=l"(d) : "l"(a), "l"(b), "l"(c));
    return d;
}

// ---------------- small losses + g_min init (one launch) ----------------
__global__ void small_losses_kernel(const float* __restrict__ pred,
                                    const float* __restrict__ targ) {
    __shared__ float red[TPB];
    const int tid = threadIdx.x;
    const int gid = blockIdx.x * TPB + tid;
    const int gsz = gridDim.x * TPB;     // 32768

    // init chamfer min slots (2*B*N = 65536 ints, 2 per thread)
    g_min[gid]       = 0x7F7F7F7F;
    g_min[gid + gsz] = 0x7F7F7F7F;

    // ---- vertex: sum (p-t)^2, vectorized float4 (98304 = 24576 float4) ----
    const float4* p4 = (const float4*)pred;
    const float4* t4 = (const float4*)targ;
    float s = 0.f;
    for (int i = gid; i < B_ * N_ * 3 / 4; i += gsz) {
        float4 a = p4[i], b = t4[i];
        float d0 = a.x - b.x, d1 = a.y - b.y, d2 = a.z - b.z, d3 = a.w - b.w;
        s = fmaf(d0, d0, fmaf(d1, d1, fmaf(d2, d2, fmaf(d3, d3, s))));
    }
    red[tid] = s; __syncthreads();
    for (int o = TPB / 2; o > 0; o >>= 1) {
        if (tid < o) red[tid] += red[tid + o];
        __syncthreads();
    }
    if (tid == 0) g_part[0 * SL_GRID + blockIdx.x] = red[0];
    __syncthreads();

    // ---- smoothness: sum ||p[k+1]-p[k]||, batch outer loop (no div) ----
    s = 0.f;
    for (int b = 0; b < B_; b++) {
        const float* pb = pred + b * N_ * 3;
        for (int k = gid; k < N_ - 1; k += gsz) {
            const float* p = pb + k * 3;
            float dx = p[3] - p[0], dy = p[4] - p[1], dz = p[5] - p[2];
            s += sqrtf(fmaf(dx, dx, fmaf(dy, dy, dz * dz)));
        }
    }
    red[tid] = s; __syncthreads();
    for (int o = TPB / 2; o > 0; o >>= 1) {
        if (tid < o) red[tid] += red[tid + o];
        __syncthreads();
    }
    if (tid == 0) g_part[1 * SL_GRID + blockIdx.x] = red[0];
    __syncthreads();

    // ---- symmetry ----
    s = 0.f;
    const int mid = N_ / 2;
    for (int b = 0; b < B_; b++) {
        const float* pb = pred + b * N_ * 3;
        for (int k = gid; k < mid; k += gsz) {
            const float* l = pb + k * 3;
            const float* r = pb + (N_ - 1 - k) * 3;
            float d0 = l[0] + r[0];
            float d1 = l[1] - r[1];
            float d2 = l[2] - r[2];
            s += fmaf(d0, d0, fmaf(d1, d1, d2 * d2));
        }
    }
    red[tid] = s; __syncthreads();
    for (int o = TPB / 2; o > 0; o >>= 1) {
        if (tid < o) red[tid] += red[tid + o];
        __syncthreads();
    }
    if (tid == 0) g_part[2 * SL_GRID + blockIdx.x] = red[0];
}

// ---------------- fused chamfer: both directions in one launch ----------------
// blockIdx.z in [0,8): b = z&3, dir = z>>2 (0: pred->targ mins, 1: targ->pred)
// smem per y: packed-dup { -2yx,-2yx }{ -2yy,-2yy }{ -2yz,-2yz }{ ||y||^2,||y||^2 }
__global__ void __launch_bounds__(TPB, 4)
chamfer_kernel(const float* __restrict__ pred, const float* __restrict__ targ) {
    __shared__ F2 sy[SEG][4];           // 16 KB

    const int b   = blockIdx.z & 3;
    const int dir = blockIdx.z >> 2;
    const float* X = dir ? targ : pred;
    const float* Y = dir ? pred : targ;
    const int outOff = dir ? (B_ * N_) : 0;

    // load + transform y segment
    const float* Yb = Y + b * N_ * 3;
    const int m0 = blockIdx.y * SEG;
    for (int j = threadIdx.x; j < SEG; j += TPB) {
        const float* y = Yb + (m0 + j) * 3;
        float y0 = y[0], y1 = y[1], y2 = y[2];
        float yw = fmaf(y0, y0, fmaf(y1, y1, y2 * y2));
        F2 a, bb, c, d;
        a.f  = make_float2(-2.f * y0, -2.f * y0);
        bb.f = make_float2(-2.f * y1, -2.f * y1);
        c.f  = make_float2(-2.f * y2, -2.f * y2);
        d.f  = make_float2(yw, yw);
        sy[j][0] = a; sy[j][1] = bb; sy[j][2] = c; sy[j][3] = d;
    }
    __syncthreads();

    // load 8 x points per thread, packed as 4 pairs (q, q+4)
    const float* Xb = X + b * N_ * 3;
    const int base = blockIdx.x * XPB + threadIdx.x;

    F2 xp0[4], xp1[4], xp2[4];
    float xnA[4], xnB[4], mnA[4], mnB[4];
#pragma unroll
    for (int q = 0; q < 4; q++) {
        const float* xa = Xb + (base + q * TPB) * 3;
        const float* xb = Xb + (base + (q + 4) * TPB) * 3;
        float a0 = xa[0], a1 = xa[1], a2 = xa[2];
        float b0 = xb[0], b1 = xb[1], b2 = xb[2];
        xp0[q].f = make_float2(a0, b0);
        xp1[q].f = make_float2(a1, b1);
        xp2[q].f = make_float2(a2, b2);
        xnA[q] = fmaf(a0, a0, fmaf(a1, a1, a2 * a2));
        xnB[q] = fmaf(b0, b0, fmaf(b1, b1, b2 * b2));
        mnA[q] = 3.0e38f; mnB[q] = 3.0e38f;
    }

    // mainloop: s = ||y||^2 - 2 x.y  via 3-deep packed-FMA chain, 2 pairs/inst
#pragma unroll 2
    for (int j = 0; j < SEG; j++) {
        const ulonglong2* row = (const ulonglong2*)&sy[j][0];
        ulonglong2 r0 = row[0];   // {-2yx | -2yy}
        ulonglong2 r1 = row[1];   // {-2yz | yw  }
#pragma unroll
        for (int q = 0; q < 4; q++) {
            F2 sres;
            sres.u = fma2(xp2[q].u, r1.x,
                      fma2(xp1[q].u, r0.y,
                       fma2(xp0[q].u, r0.x, r1.y)));
            mnA[q] = fminf(mnA[q], sres.f.x);
            mnB[q] = fminf(mnB[q], sres.f.y);
        }
    }

#pragma unroll
    for (int q = 0; q < 4; q++) {
        float d2a = fmaxf(xnA[q] + mnA[q], 0.f);
        float d2b = fmaxf(xnB[q] + mnB[q], 0.f);
        atomicMin(&g_min[outOff + b * N_ + base + q * TPB],       __float_as_int(d2a));
        atomicMin(&g_min[outOff + b * N_ + base + (q + 4) * TPB], __float_as_int(d2b));
    }
}

// ---------------- finalize ----------------
__global__ void finalize_kernel(float* __restrict__ out) {
    __shared__ float red[FTPB];
    __shared__ float sums[4];
    const int tid = threadIdx.x;

    // chamfer: sum sqrt(min d2), int4-vectorized (65536 ints = 16384 int4)
    float s = 0.f;
    const int4* gm4 = (const int4*)g_min;
    for (int i = tid; i < 2 * B_ * N_ / 4; i += FTPB) {
        int4 v = gm4[i];
        s += sqrtf(__int_as_float(v.x)) + sqrtf(__int_as_float(v.y))
           + sqrtf(__int_as_float(v.z)) + sqrtf(__int_as_float(v.w));
    }
    red[tid] = s; __syncthreads();
    for (int o = FTPB / 2; o > 0; o >>= 1) {
        if (tid < o) red[tid] += red[tid + o];
        __syncthreads();
    }
    if (tid == 0) sums[3] = red[0];
    __syncthreads();

#pragma unroll
    for (int t = 0; t < 3; t++) {
        s = (tid < SL_GRID) ? g_part[t * SL_GRID + tid] : 0.f;
        red[tid] = s; __syncthreads();
        for (int o = FTPB / 2; o > 0; o >>= 1) {
            if (tid < o) red[tid] += red[tid + o];
            __syncthreads();
        }
        if (tid == 0) sums[t] = red[0];
        __syncthreads();
    }

    if (tid == 0) {
        float vertex_loss  = sums[0] / (float)(B_ * N_ * 3);
        float smooth_loss  = sums[1] / (float)(B_ * (N_ - 1));
        float sym_loss     = sums[2] / (float)(B_ * (N_ / 2) * 3);
        float chamfer_loss = sums[3] / (float)(B_ * N_);
        out[0] = 1.0f * vertex_loss + 0.1f * smooth_loss
               + 0.05f * sym_loss + 0.1f * chamfer_loss;
    }
}

extern "C" void kernel_launch(void* const* d_in, const int* in_sizes, int n_in,
                              void* d_out, int out_size) {
    const float* pred = (const float*)d_in[0];
    const float* targ = (const float*)d_in[1];
    float* out = (float*)d_out;
    (void)in_sizes; (void)n_in; (void)out_size;

    small_losses_kernel<<<SL_GRID, TPB>>>(pred, targ);   // also inits g_min

    dim3 grid(XTILES, NSEG, B_ * 2);                     // both directions fused
    chamfer_kernel<<<grid, TPB>>>(pred, targ);

    finalize_kernel<<<1, FTPB>>>(out);
}